// round 2
// baseline (speedup 1.0000x reference)
#include <cuda_runtime.h>

#define D      256
#define Kc     1024
#define NROWS  32768
#define Z_ELEMS 8388608

#define TM 64
#define TN 64
#define TK 16
#define BS_STRIDE 68   // 64 + 4 pad: keeps 16B alignment, kills bank conflicts

__device__ float g_cnorm[Kc];
__device__ float g_znorm[NROWS];
__device__ int   g_idx[NROWS];
__device__ float g_loss;

// ---------------------------------------------------------------------------
// k0: per-code squared norms, sequential ascending fp32, UNFUSED mul+add
// (replicates jnp.sum(codebook*codebook, axis=1) on XLA CPU). Also resets loss.
// ---------------------------------------------------------------------------
__global__ void prep_kernel(const float* __restrict__ cb) {
    int k = blockIdx.x * blockDim.x + threadIdx.x;
    if (k == 0 && blockIdx.x == 0) g_loss = 0.0f;
    if (k < Kc) {
        const float* row = cb + (size_t)k * D;
        float s = 0.0f;
        for (int i = 0; i < D; ++i) {
            float v = row[i];
            s = __fadd_rn(s, __fmul_rn(v, v));   // no FMA contraction
        }
        g_cnorm[k] = s;
    }
}

// ---------------------------------------------------------------------------
// k0b: per-row squared norms zn[n] = sum_d z[b,d,hw]^2, sequential ascending d,
// UNFUSED fp32 mul+add — must be bit-exact vs reference (zn's bits set the
// ulp(256) quantization grid for every score in the row).
// ---------------------------------------------------------------------------
__global__ void znorm_kernel(const float* __restrict__ z) {
    int n = blockIdx.x * blockDim.x + threadIdx.x;   // n = b*1024 + hw
    int b  = n >> 10;
    int hw = n & 1023;
    const float* base = z + (size_t)b * (D * 1024) + hw;
    float s = 0.0f;
    #pragma unroll 8
    for (int d = 0; d < D; ++d) {
        float v = base[(size_t)d * 1024];
        s = __fadd_rn(s, __fmul_rn(v, v));
    }
    g_znorm[n] = s;
}

// ---------------------------------------------------------------------------
// k1: fused distance-GEMM + argmin, replicating reference numerics:
//   dot  = sequential ascending-d fp32 FMA chain (single accumulator)
//   d_k  = fl( fl(zn + cn_k) - fl(2*dot) )      (reference op order, unfused)
//   argmin: ascending code order, strict <  (first-occurrence ties)
// ---------------------------------------------------------------------------
__global__ void __launch_bounds__(256, 2)
argmin_kernel(const float* __restrict__ z, const float* __restrict__ cb,
              float* __restrict__ out_idx_f) {
    extern __shared__ float sm[];
    float* Zs     = sm;                       // [256][64]
    float* Bs     = Zs + D * TM;              // [16][BS_STRIDE]
    float* red_s  = Bs + TK * BS_STRIDE;      // [16][64]
    int*   red_i  = (int*)(red_s + 16 * TM);  // [16][64]
    float* best_s = (float*)(red_i + 16 * TM);// [64]
    int*   best_i = (int*)(best_s + TM);      // [64]
    float* zn_s   = (float*)(best_i + TM);    // [64]

    const int t  = threadIdx.x;
    const int tx = t & 15;    // row group: rows = tx*4 + i
    const int ty = t >> 4;    // code group: codes = ty*4 + j
    const int n0 = blockIdx.x * TM;
    const int b  = n0 >> 10;
    const int hw = n0 & 1023;
    const float* zb = z + (size_t)b * (D * 1024) + hw;

    for (int i = t; i < D * TM; i += 256) {
        int d = i >> 6, r = i & 63;
        Zs[i] = zb[(size_t)d * 1024 + r];
    }
    if (t < TM) {
        best_s[t] = 3.4e38f;
        best_i[t] = 0;
        zn_s[t]   = g_znorm[n0 + t];
    }
    __syncthreads();

    for (int ct = 0; ct < Kc / TN; ++ct) {
        float acc[4][4] = {};
        const float* cbt = cb + (size_t)(ct * TN) * D;

        for (int d0 = 0; d0 < D; d0 += TK) {
            {
                int d  = t & 15;
                int c0 = t >> 4;
                #pragma unroll
                for (int cc = 0; cc < 4; ++cc) {
                    int c = c0 + cc * 16;
                    Bs[d * BS_STRIDE + c] = cbt[(size_t)c * D + d0 + d];
                }
            }
            __syncthreads();
            #pragma unroll
            for (int k = 0; k < TK; ++k) {
                float a[4], bq[4];
                *(float4*)a  = *(const float4*)&Zs[(d0 + k) * TM + (tx << 2)];
                *(float4*)bq = *(const float4*)&Bs[k * BS_STRIDE + (ty << 2)];
                #pragma unroll
                for (int i = 0; i < 4; ++i)
                    #pragma unroll
                    for (int j = 0; j < 4; ++j)
                        acc[i][j] = fmaf(a[i], bq[j], acc[i][j]);  // sequential ascending d
            }
            __syncthreads();
        }

        float cn[4];
        #pragma unroll
        for (int j = 0; j < 4; ++j) cn[j] = g_cnorm[ct * TN + (ty << 2) + j];

        #pragma unroll
        for (int i = 0; i < 4; ++i) {
            int row = (tx << 2) + i;
            float zn = zn_s[row];
            float bs;
            int   bj = 0;
            {   // reference op order: t1 = fl(zn+cn); d = fl(t1 - fl(2*dot))
                float t1 = __fadd_rn(zn, cn[0]);
                bs = __fadd_rn(t1, __fmul_rn(-2.0f, acc[i][0]));
            }
            #pragma unroll
            for (int j = 1; j < 4; ++j) {
                float t1 = __fadd_rn(zn, cn[j]);
                float s  = __fadd_rn(t1, __fmul_rn(-2.0f, acc[i][j]));
                if (s < bs) { bs = s; bj = j; }
            }
            red_s[ty * TM + row] = bs;
            red_i[ty * TM + row] = ct * TN + (ty << 2) + bj;
        }
        __syncthreads();
        if (t < TM) {
            float bs = best_s[t]; int bi = best_i[t];
            #pragma unroll
            for (int g = 0; g < 16; ++g) {     // g ascending == code ascending
                float s = red_s[g * TM + t];
                if (s < bs) { bs = s; bi = red_i[g * TM + t]; }
            }
            best_s[t] = bs; best_i[t] = bi;
        }
        __syncthreads();
    }

    if (t < TM) {
        int n = n0 + t;
        g_idx[n]     = best_i[t];
        out_idx_f[n] = (float)best_i[t];
    }
}

// ---------------------------------------------------------------------------
// k2: gather + straight-through output + loss partial sums.
// out = fl(z + fl(q - z))  — elementwise identical to reference STE.
// ---------------------------------------------------------------------------
__global__ void gather_kernel(const float* __restrict__ z, const float* __restrict__ cb,
                              float* __restrict__ out) {
    int e = blockIdx.x * blockDim.x + threadIdx.x;   // NCHW linear
    int bb = e >> 18;
    int d  = (e >> 10) & 255;
    int hw = e & 1023;
    int n  = (bb << 10) + hw;
    int ci = g_idx[n];
    float q    = cb[(size_t)ci * D + d];
    float zv   = z[e];
    float diff = __fadd_rn(q, -zv);
    out[e] = __fadd_rn(zv, diff);
    float part = diff * diff;

    __shared__ float rs[256];
    rs[threadIdx.x] = part;
    __syncthreads();
    #pragma unroll
    for (int s = 128; s > 0; s >>= 1) {
        if (threadIdx.x < s) rs[threadIdx.x] += rs[threadIdx.x + s];
        __syncthreads();
    }
    if (threadIdx.x == 0) atomicAdd(&g_loss, rs[0]);
}

// k3: loss = (1 + 0.25) * mean((q - z)^2)
__global__ void fin_kernel(float* __restrict__ out) {
    out[Z_ELEMS + NROWS] = 1.25f * g_loss / (float)Z_ELEMS;
}

// ---------------------------------------------------------------------------
extern "C" void kernel_launch(void* const* d_in, const int* in_sizes, int n_in,
                              void* d_out, int out_size) {
    const float* z  = (const float*)d_in[0];
    const float* cb = (const float*)d_in[1];
    float* out = (float*)d_out;

    const int smem_bytes =
        (D * TM + TK * BS_STRIDE + 16 * TM) * 4   // Zs + Bs + red_s
        + 16 * TM * 4                              // red_i
        + TM * 4 + TM * 4 + TM * 4;                // best_s + best_i + zn_s

    cudaFuncSetAttribute(argmin_kernel,
                         cudaFuncAttributeMaxDynamicSharedMemorySize, smem_bytes);

    prep_kernel<<<4, 256>>>(cb);
    znorm_kernel<<<NROWS / 256, 256>>>(z);
    argmin_kernel<<<NROWS / TM, 256, smem_bytes>>>(z, cb, out + Z_ELEMS);
    gather_kernel<<<Z_ELEMS / 256, 256>>>(z, cb, out);
    fin_kernel<<<1, 1>>>(out);
}